// round 1
// baseline (speedup 1.0000x reference)
#include <cuda_runtime.h>

#define NN   20000
#define EE   640000
#define HH   128
#define TILE 64
#define PAD  132
#define NTHR 256

// Scratch (allocation-free rule: __device__ globals)
__device__ __align__(16) float g_m_i[NN * HH];   // segment-summed m_ij
__device__ __align__(16) float g_xupd[NN * 3];   // segment-summed coord update
__device__ int g_is64;                            // edge_index dtype flag

__device__ __forceinline__ float silu_f(float v) {
    return v * (1.0f / (1.0f + __expf(-v)));
}

// acc[4][8] += Sin[64][PAD](cols 0..127) @ W[128][128]  (W row-major, k-major)
// wbuf: smem staging [16][128]. Syncs internally; first sync also orders any
// prior smem writes by the whole block before Sin is read.
__device__ __forceinline__ void gemm_acc(float acc[4][8],
                                         const float* __restrict__ W,
                                         const float* __restrict__ Sin,
                                         float* __restrict__ wbuf,
                                         int tid, int r0, int c0)
{
#pragma unroll 1
    for (int k0 = 0; k0 < 128; k0 += 16) {
        __syncthreads();                      // prior wbuf readers done
        const float4* Wg = (const float4*)(W + k0 * HH);
        ((float4*)wbuf)[tid]       = Wg[tid];
        ((float4*)wbuf)[tid + 256] = Wg[tid + 256];
        __syncthreads();
#pragma unroll
        for (int kk = 0; kk < 16; kk++) {
            float4 b0 = *(const float4*)&wbuf[kk * HH + c0];
            float4 b1 = *(const float4*)&wbuf[kk * HH + c0 + 4];
            float bb[8] = {b0.x, b0.y, b0.z, b0.w, b1.x, b1.y, b1.z, b1.w};
            float aa[4];
#pragma unroll
            for (int i = 0; i < 4; i++) aa[i] = Sin[(r0 + i) * PAD + k0 + kk];
#pragma unroll
            for (int i = 0; i < 4; i++)
#pragma unroll
                for (int j = 0; j < 8; j++)
                    acc[i][j] += aa[i] * bb[j];
        }
    }
}

// ---------------------------------------------------------------------------
// Kernel 0: zero accumulators + detect edge_index width (int32 vs int64)
// ---------------------------------------------------------------------------
__global__ void zero_kernel(const void* ei) {
    int i = blockIdx.x * blockDim.x + threadIdx.x;
    const int total = NN * HH + NN * 3;
    if (i < total) {
        if (i < NN * HH) g_m_i[i] = 0.0f;
        else             g_xupd[i - NN * HH] = 0.0f;
    }
    if (blockIdx.x == 0 && threadIdx.x == 0) {
        // If int64 (little-endian), high words of small positive indices are 0.
        const unsigned* w = (const unsigned*)ei;
        int is64 = 1;
        for (int k = 0; k < 32; k++)
            if (w[2 * k + 1] != 0u) { is64 = 0; break; }
        g_is64 = is64;
    }
}

// ---------------------------------------------------------------------------
// Kernel 1: fused edge pipeline.
//  feat=[h[row],h[col],radial] -> silu(silu(.@ew1+eb1)@ew2+eb2)=m_ij
//  cw = silu(m_ij@cw1+cb1)@cw2 ;  atomic m_i += m_ij ; x_upd += cd*cw
// ---------------------------------------------------------------------------
__global__ void __launch_bounds__(NTHR, 2) edge_kernel(
    const float* __restrict__ h, const float* __restrict__ x,
    const void* __restrict__ ei,
    const float* __restrict__ ew1, const float* __restrict__ eb1,
    const float* __restrict__ ew2, const float* __restrict__ eb2,
    const float* __restrict__ cw1, const float* __restrict__ cb1,
    const float* __restrict__ cw2)
{
    extern __shared__ float smem[];
    float* S_hr  = smem;                    // [64][132]
    float* S_hc  = S_hr + TILE * PAD;       // [64][132]
    float* S_act = S_hc + TILE * PAD;       // [64][132]
    float* wbuf  = S_act + TILE * PAD;      // [16][128]
    float* s_rad = wbuf + 16 * HH;          // [64]
    float* s_cw  = s_rad + TILE;            // [64]
    float* s_cd  = s_cw + TILE;             // [64][3]
    int*   s_row = (int*)(s_cd + TILE * 3); // [64]
    int*   s_col = s_row + TILE;            // [64]

    const int tid = threadIdx.x;
    const int e0  = blockIdx.x * TILE;

    if (tid < TILE) {
        int e = e0 + tid;
        int r, c;
        if (g_is64) {
            const long long* p = (const long long*)ei;
            r = (int)p[e]; c = (int)p[EE + e];
        } else {
            const int* p = (const int*)ei;
            r = p[e]; c = p[EE + e];
        }
        s_row[tid] = r; s_col[tid] = c;
        float dx = x[r * 3 + 0] - x[c * 3 + 0];
        float dy = x[r * 3 + 1] - x[c * 3 + 1];
        float dz = x[r * 3 + 2] - x[c * 3 + 2];
        s_cd[tid * 3 + 0] = dx; s_cd[tid * 3 + 1] = dy; s_cd[tid * 3 + 2] = dz;
        s_rad[tid] = dx * dx + dy * dy + dz * dz;
    }
    __syncthreads();

    // Gather h[row], h[col] tiles (float4)
    const float4* h4 = (const float4*)h;
    for (int i = tid; i < TILE * 32; i += NTHR) {
        int e = i >> 5, q = i & 31;
        *(float4*)&S_hr[e * PAD + q * 4] = h4[s_row[e] * 32 + q];
        *(float4*)&S_hc[e * PAD + q * 4] = h4[s_col[e] * 32 + q];
    }

    const int r0 = (tid >> 4) * 4;
    const int c0 = (tid & 15) * 8;
    float acc[4][8];

    // GEMM1 init: eb1 + radial * ew1[256,:]
    const float* wlast = ew1 + 256 * HH;
#pragma unroll
    for (int j = 0; j < 8; j++) {
        float b  = eb1[c0 + j];
        float wl = wlast[c0 + j];
#pragma unroll
        for (int i = 0; i < 4; i++) acc[i][j] = b + s_rad[r0 + i] * wl;
    }
    gemm_acc(acc, ew1,            S_hr, wbuf, tid, r0, c0);   // h[row] part
    gemm_acc(acc, ew1 + 128 * HH, S_hc, wbuf, tid, r0, c0);   // h[col] part

    // silu -> S_act (fresh buffer; gemm's first sync orders it for readers)
#pragma unroll
    for (int i = 0; i < 4; i++)
#pragma unroll
        for (int j = 0; j < 8; j++)
            S_act[(r0 + i) * PAD + c0 + j] = silu_f(acc[i][j]);

    // GEMM2
#pragma unroll
    for (int j = 0; j < 8; j++) {
        float b = eb2[c0 + j];
#pragma unroll
        for (int i = 0; i < 4; i++) acc[i][j] = b;
    }
    gemm_acc(acc, ew2, S_act, wbuf, tid, r0, c0);

    // m_ij = silu -> S_hr (all S_hr readers are past gemm2's syncs)
#pragma unroll
    for (int i = 0; i < 4; i++)
#pragma unroll
        for (int j = 0; j < 8; j++)
            S_hr[(r0 + i) * PAD + c0 + j] = silu_f(acc[i][j]);

    // GEMM3 (coord_mlp layer 1)
#pragma unroll
    for (int j = 0; j < 8; j++) {
        float b = cb1[c0 + j];
#pragma unroll
        for (int i = 0; i < 4; i++) acc[i][j] = b;
    }
    gemm_acc(acc, cw1, S_hr, wbuf, tid, r0, c0);

    // coord_weight = silu(t) @ cw2  — in-register, 16-lane shfl reduce
    float cwr[8];
#pragma unroll
    for (int j = 0; j < 8; j++) cwr[j] = cw2[c0 + j];
#pragma unroll
    for (int i = 0; i < 4; i++) {
        float p = 0.0f;
#pragma unroll
        for (int j = 0; j < 8; j++) p += silu_f(acc[i][j]) * cwr[j];
#pragma unroll
        for (int off = 8; off >= 1; off >>= 1)
            p += __shfl_down_sync(0xffffffffu, p, off);
        if ((tid & 15) == 0) s_cw[r0 + i] = p;
    }
    __syncthreads();

    // Scatter: coordinate update
    if (tid < TILE) {
        int r = s_row[tid];
        float w = s_cw[tid];
        atomicAdd(&g_xupd[r * 3 + 0], s_cd[tid * 3 + 0] * w);
        atomicAdd(&g_xupd[r * 3 + 1], s_cd[tid * 3 + 1] * w);
        atomicAdd(&g_xupd[r * 3 + 2], s_cd[tid * 3 + 2] * w);
    }
    // Scatter: m_i (coalesced 32-wide per edge)
    for (int i = tid; i < TILE * HH; i += NTHR) {
        int e = i >> 7, cc = i & 127;
        atomicAdd(&g_m_i[s_row[e] * HH + cc], S_hr[e * PAD + cc]);
    }
}

// ---------------------------------------------------------------------------
// Kernel 2: node MLP + residual, plus x_new epilogue
// ---------------------------------------------------------------------------
__global__ void __launch_bounds__(NTHR, 2) node_kernel(
    const float* __restrict__ h, const float* __restrict__ x,
    const float* __restrict__ nw1, const float* __restrict__ nb1,
    const float* __restrict__ nw2, const float* __restrict__ nb2,
    float* __restrict__ out)
{
    extern __shared__ float smem[];
    float* S_h   = smem;
    float* S_m   = S_h + TILE * PAD;
    float* S_act = S_m + TILE * PAD;
    float* wbuf  = S_act + TILE * PAD;

    const int tid = threadIdx.x;
    const int n0  = blockIdx.x * TILE;

    const float4* h4 = (const float4*)h;
    const float4* m4 = (const float4*)g_m_i;
    for (int i = tid; i < TILE * 32; i += NTHR) {
        int rl = i >> 5, q = i & 31;
        int r = n0 + rl;
        float4 vh = make_float4(0.f, 0.f, 0.f, 0.f);
        float4 vm = vh;
        if (r < NN) { vh = h4[r * 32 + q]; vm = m4[r * 32 + q]; }
        *(float4*)&S_h[rl * PAD + q * 4] = vh;
        *(float4*)&S_m[rl * PAD + q * 4] = vm;
    }

    const int r0 = (tid >> 4) * 4;
    const int c0 = (tid & 15) * 8;
    float acc[4][8];

#pragma unroll
    for (int j = 0; j < 8; j++) {
        float b = nb1[c0 + j];
#pragma unroll
        for (int i = 0; i < 4; i++) acc[i][j] = b;
    }
    gemm_acc(acc, nw1,            S_h, wbuf, tid, r0, c0);
    gemm_acc(acc, nw1 + 128 * HH, S_m, wbuf, tid, r0, c0);

#pragma unroll
    for (int i = 0; i < 4; i++)
#pragma unroll
        for (int j = 0; j < 8; j++)
            S_act[(r0 + i) * PAD + c0 + j] = silu_f(acc[i][j]);

#pragma unroll
    for (int j = 0; j < 8; j++) {
        float b = nb2[c0 + j];
#pragma unroll
        for (int i = 0; i < 4; i++) acc[i][j] = b;
    }
    gemm_acc(acc, nw2, S_act, wbuf, tid, r0, c0);

    // h_new = h + out2
#pragma unroll
    for (int i = 0; i < 4; i++) {
        int r = n0 + r0 + i;
        if (r < NN) {
#pragma unroll
            for (int j = 0; j < 8; j++)
                out[r * HH + c0 + j] = S_h[(r0 + i) * PAD + c0 + j] + acc[i][j];
        }
    }

    // x_new = x + x_update / (N-1)
    if (tid < TILE) {
        int r = n0 + tid;
        if (r < NN) {
            const float inv = 1.0f / (float)(NN - 1);
            out[NN * HH + r * 3 + 0] = x[r * 3 + 0] + g_xupd[r * 3 + 0] * inv;
            out[NN * HH + r * 3 + 1] = x[r * 3 + 1] + g_xupd[r * 3 + 1] * inv;
            out[NN * HH + r * 3 + 2] = x[r * 3 + 2] + g_xupd[r * 3 + 2] * inv;
        }
    }
}

// ---------------------------------------------------------------------------

extern "C" void kernel_launch(void* const* d_in, const int* in_sizes, int n_in,
                              void* d_out, int out_size) {
    const float* h   = (const float*)d_in[0];
    const float* x   = (const float*)d_in[1];
    const void*  ei  = d_in[2];                 // int32 or int64, detected on device
    const float* ew1 = (const float*)d_in[3];
    const float* eb1 = (const float*)d_in[4];
    const float* ew2 = (const float*)d_in[5];
    const float* eb2 = (const float*)d_in[6];
    const float* nw1 = (const float*)d_in[7];
    const float* nb1 = (const float*)d_in[8];
    const float* nw2 = (const float*)d_in[9];
    const float* nb2 = (const float*)d_in[10];
    const float* cw1 = (const float*)d_in[11];
    const float* cb1 = (const float*)d_in[12];
    const float* cw2 = (const float*)d_in[13];
    float* out = (float*)d_out;

    const int smem_edge = (3 * TILE * PAD + 16 * HH + TILE * 5 + TILE * 3) * 4 + 256;
    const int smem_node = (3 * TILE * PAD + 16 * HH) * 4;

    cudaFuncSetAttribute(edge_kernel, cudaFuncAttributeMaxDynamicSharedMemorySize, smem_edge);
    cudaFuncSetAttribute(node_kernel, cudaFuncAttributeMaxDynamicSharedMemorySize, smem_node);

    const int total = NN * HH + NN * 3;
    zero_kernel<<<(total + 1023) / 1024, 1024>>>(ei);
    edge_kernel<<<EE / TILE, NTHR, smem_edge>>>(h, x, ei, ew1, eb1, ew2, eb2,
                                                cw1, cb1, cw2);
    node_kernel<<<(NN + TILE - 1) / TILE, NTHR, smem_node>>>(h, x, nw1, nb1,
                                                             nw2, nb2, out);
}

// round 3
// speedup vs baseline: 1.3118x; 1.3118x over previous
#include <cuda_runtime.h>

#define NN   20000
#define EE   640000
#define HH   128
#define TILE 64
#define PAD  132
#define NTHR 256

typedef unsigned long long u64;

// Scratch (allocation-free rule: __device__ globals)
__device__ __align__(16) float g_m_i[NN * HH];   // segment-summed m_ij
__device__ __align__(16) float g_xupd[NN * 3];   // segment-summed coord update
__device__ int g_is64;                            // edge_index dtype flag

__device__ __forceinline__ float silu_f(float v) {
    return v * (1.0f / (1.0f + __expf(-v)));
}

// packed fp32x2 FMA: d.lo += a.lo*b.lo ; d.hi += a.hi*b.hi
__device__ __forceinline__ void fma2(u64& d, u64 a, u64 b) {
    asm("fma.rn.f32x2 %0, %1, %2, %0;" : "+l"(d) : "l"(a), "l"(b));
}
__device__ __forceinline__ float red2(u64 v) {
    return __uint_as_float((unsigned)v) + __uint_as_float((unsigned)(v >> 32));
}

// acc[4][8] (f32x2, lo=even-k partial, hi=odd-k partial) +=
//   Sin[64][PAD](cols 0..127) @ W[128][128] (W row-major, k-major, global)
// Weights are staged per 16-k chunk into wbuf2 INTERLEAVED as k-pairs:
//   wbuf2[k2*128 + j] = (W[2k2][j], W[2k2+1][j])
// Thread (r0, c0): rows r0..r0+3, cols c0+16*m (m=0..7).
// Syncs internally; first sync also orders prior smem writes by the block.
__device__ __forceinline__ void gemm2(u64 acc[4][8],
                                      const float* __restrict__ W,
                                      const float* __restrict__ Sin,
                                      float2* __restrict__ wbuf2,
                                      int tid, int r0, int c0)
{
#pragma unroll 1
    for (int k0 = 0; k0 < 128; k0 += 16) {
        __syncthreads();                      // prior wbuf2 readers done
#pragma unroll
        for (int t = 0; t < 4; t++) {
            int idx = tid + t * 256;          // 0..1023 over [8][128]
            int k2 = idx >> 7, j = idx & 127;
            wbuf2[idx] = make_float2(W[(k0 + 2 * k2) * HH + j],
                                     W[(k0 + 2 * k2 + 1) * HH + j]);
        }
        __syncthreads();
#pragma unroll
        for (int k2 = 0; k2 < 8; k2++) {
            u64 bb[8], aa[4];
#pragma unroll
            for (int m = 0; m < 8; m++)
                bb[m] = *(const u64*)&wbuf2[k2 * 128 + c0 + 16 * m];
#pragma unroll
            for (int i = 0; i < 4; i++)
                aa[i] = *(const u64*)&Sin[(r0 + i) * PAD + k0 + 2 * k2];
#pragma unroll
            for (int i = 0; i < 4; i++)
#pragma unroll
                for (int m = 0; m < 8; m++)
                    fma2(acc[i][m], aa[i], bb[m]);
        }
    }
}

// ---------------------------------------------------------------------------
// Kernel 0: zero accumulators + detect edge_index width (int32 vs int64)
// ---------------------------------------------------------------------------
__global__ void zero_kernel(const void* ei) {
    int i = blockIdx.x * blockDim.x + threadIdx.x;
    const int total = NN * HH + NN * 3;
    if (i < total) {
        if (i < NN * HH) g_m_i[i] = 0.0f;
        else             g_xupd[i - NN * HH] = 0.0f;
    }
    if (blockIdx.x == 0 && threadIdx.x == 0) {
        const unsigned* w = (const unsigned*)ei;
        int is64 = 1;
        for (int k = 0; k < 32; k++)
            if (w[2 * k + 1] != 0u) { is64 = 0; break; }
        g_is64 = is64;
    }
}

// ---------------------------------------------------------------------------
// Kernel 1: fused edge pipeline.
// ---------------------------------------------------------------------------
__global__ void __launch_bounds__(NTHR, 2) edge_kernel(
    const float* __restrict__ h, const float* __restrict__ x,
    const void* __restrict__ ei,
    const float* __restrict__ ew1, const float* __restrict__ eb1,
    const float* __restrict__ ew2, const float* __restrict__ eb2,
    const float* __restrict__ cw1, const float* __restrict__ cb1,
    const float* __restrict__ cw2)
{
    extern __shared__ float smem[];
    float*  S_hr  = smem;                     // [64][132]
    float*  S_hc  = S_hr + TILE * PAD;        // [64][132]
    float*  S_act = S_hc + TILE * PAD;        // [64][132]
    float2* wbuf2 = (float2*)(S_act + TILE * PAD);   // [8][128] f32x2
    float*  s_rad = (float*)(wbuf2 + 8 * HH); // [64]
    float*  s_cw  = s_rad + TILE;             // [64]
    float*  s_cd  = s_cw + TILE;              // [64][3]
    int*    s_row = (int*)(s_cd + TILE * 3);  // [64]
    int*    s_col = s_row + TILE;             // [64]

    const int tid = threadIdx.x;
    const int e0  = blockIdx.x * TILE;

    if (tid < TILE) {
        int e = e0 + tid;
        int r, c;
        if (g_is64) {
            const long long* p = (const long long*)ei;
            r = (int)p[e]; c = (int)p[EE + e];
        } else {
            const int* p = (const int*)ei;
            r = p[e]; c = p[EE + e];
        }
        s_row[tid] = r; s_col[tid] = c;
        float dx = x[r * 3 + 0] - x[c * 3 + 0];
        float dy = x[r * 3 + 1] - x[c * 3 + 1];
        float dz = x[r * 3 + 2] - x[c * 3 + 2];
        s_cd[tid * 3 + 0] = dx; s_cd[tid * 3 + 1] = dy; s_cd[tid * 3 + 2] = dz;
        s_rad[tid] = dx * dx + dy * dy + dz * dz;
    }
    __syncthreads();

    // Gather h[row], h[col] tiles (float4)
    const float4* h4 = (const float4*)h;
    for (int i = tid; i < TILE * 32; i += NTHR) {
        int e = i >> 5, q = i & 31;
        *(float4*)&S_hr[e * PAD + q * 4] = h4[s_row[e] * 32 + q];
        *(float4*)&S_hc[e * PAD + q * 4] = h4[s_col[e] * 32 + q];
    }

    const int r0 = (tid >> 4) * 4;   // row group
    const int c0 = tid & 15;         // column base; cols = c0 + 16*m
    u64 acc[4][8];

    // GEMM1 init: eb1 + radial * ew1[256,:]  (both f32x2 halves get half init?
    // No: put full init in lo-half, hi starts at 0, sum at reduction.)
    const float* wlast = ew1 + 256 * HH;
#pragma unroll
    for (int m = 0; m < 8; m++) {
        float b  = eb1[c0 + 16 * m];
        float wl = wlast[c0 + 16 * m];
#pragma unroll
        for (int i = 0; i < 4; i++) {
            float init = b + s_rad[r0 + i] * wl;
            acc[i][m] = (u64)__float_as_uint(init);   // lo=init, hi=0
        }
    }
    gemm2(acc, ew1,            S_hr, wbuf2, tid, r0, c0);   // h[row] part
    gemm2(acc, ew1 + 128 * HH, S_hc, wbuf2, tid, r0, c0);   // h[col] part

    // silu -> S_act
#pragma unroll
    for (int i = 0; i < 4; i++)
#pragma unroll
        for (int m = 0; m < 8; m++)
            S_act[(r0 + i) * PAD + c0 + 16 * m] = silu_f(red2(acc[i][m]));

    // GEMM2
#pragma unroll
    for (int m = 0; m < 8; m++) {
        float b = eb2[c0 + 16 * m];
#pragma unroll
        for (int i = 0; i < 4; i++) acc[i][m] = (u64)__float_as_uint(b);
    }
    gemm2(acc, ew2, S_act, wbuf2, tid, r0, c0);

    // m_ij = silu -> S_hr (gemm2's internal syncs passed all S_hr readers)
#pragma unroll
    for (int i = 0; i < 4; i++)
#pragma unroll
        for (int m = 0; m < 8; m++)
            S_hr[(r0 + i) * PAD + c0 + 16 * m] = silu_f(red2(acc[i][m]));

    // GEMM3 (coord_mlp layer 1)
#pragma unroll
    for (int m = 0; m < 8; m++) {
        float b = cb1[c0 + 16 * m];
#pragma unroll
        for (int i = 0; i < 4; i++) acc[i][m] = (u64)__float_as_uint(b);
    }
    gemm2(acc, cw1, S_hr, wbuf2, tid, r0, c0);

    // coord_weight = silu(t) @ cw2  — in-register, 16-lane shfl reduce
    float cwr[8];
#pragma unroll
    for (int m = 0; m < 8; m++) cwr[m] = cw2[c0 + 16 * m];
#pragma unroll
    for (int i = 0; i < 4; i++) {
        float p = 0.0f;
#pragma unroll
        for (int m = 0; m < 8; m++) p += silu_f(red2(acc[i][m])) * cwr[m];
#pragma unroll
        for (int off = 8; off >= 1; off >>= 1)
            p += __shfl_down_sync(0xffffffffu, p, off);
        if ((tid & 15) == 0) s_cw[r0 + i] = p;
    }
    __syncthreads();

    // Scatter: coordinate update
    if (tid < TILE) {
        int r = s_row[tid];
        float w = s_cw[tid];
        atomicAdd(&g_xupd[r * 3 + 0], s_cd[tid * 3 + 0] * w);
        atomicAdd(&g_xupd[r * 3 + 1], s_cd[tid * 3 + 1] * w);
        atomicAdd(&g_xupd[r * 3 + 2], s_cd[tid * 3 + 2] * w);
    }
    // Scatter: m_i (coalesced 32-wide per edge)
    for (int i = tid; i < TILE * HH; i += NTHR) {
        int e = i >> 7, cc = i & 127;
        atomicAdd(&g_m_i[s_row[e] * HH + cc], S_hr[e * PAD + cc]);
    }
}

// ---------------------------------------------------------------------------
// Kernel 2: node MLP + residual, plus x_new epilogue
// ---------------------------------------------------------------------------
__global__ void __launch_bounds__(NTHR, 2) node_kernel(
    const float* __restrict__ h, const float* __restrict__ x,
    const float* __restrict__ nw1, const float* __restrict__ nb1,
    const float* __restrict__ nw2, const float* __restrict__ nb2,
    float* __restrict__ out)
{
    extern __shared__ float smem[];
    float*  S_h   = smem;
    float*  S_m   = S_h + TILE * PAD;
    float*  S_act = S_m + TILE * PAD;
    float2* wbuf2 = (float2*)(S_act + TILE * PAD);

    const int tid = threadIdx.x;
    const int n0  = blockIdx.x * TILE;

    const float4* h4 = (const float4*)h;
    const float4* m4 = (const float4*)g_m_i;
    for (int i = tid; i < TILE * 32; i += NTHR) {
        int rl = i >> 5, q = i & 31;
        int r = n0 + rl;
        float4 vh = make_float4(0.f, 0.f, 0.f, 0.f);
        float4 vm = vh;
        if (r < NN) { vh = h4[r * 32 + q]; vm = m4[r * 32 + q]; }
        *(float4*)&S_h[rl * PAD + q * 4] = vh;
        *(float4*)&S_m[rl * PAD + q * 4] = vm;
    }

    const int r0 = (tid >> 4) * 4;
    const int c0 = tid & 15;
    u64 acc[4][8];

#pragma unroll
    for (int m = 0; m < 8; m++) {
        float b = nb1[c0 + 16 * m];
#pragma unroll
        for (int i = 0; i < 4; i++) acc[i][m] = (u64)__float_as_uint(b);
    }
    gemm2(acc, nw1,            S_h, wbuf2, tid, r0, c0);
    gemm2(acc, nw1 + 128 * HH, S_m, wbuf2, tid, r0, c0);

#pragma unroll
    for (int i = 0; i < 4; i++)
#pragma unroll
        for (int m = 0; m < 8; m++)
            S_act[(r0 + i) * PAD + c0 + 16 * m] = silu_f(red2(acc[i][m]));

#pragma unroll
    for (int m = 0; m < 8; m++) {
        float b = nb2[c0 + 16 * m];
#pragma unroll
        for (int i = 0; i < 4; i++) acc[i][m] = (u64)__float_as_uint(b);
    }
    gemm2(acc, nw2, S_act, wbuf2, tid, r0, c0);

    // h_new = h + out2
#pragma unroll
    for (int i = 0; i < 4; i++) {
        int r = n0 + r0 + i;
        if (r < NN) {
#pragma unroll
            for (int m = 0; m < 8; m++)
                out[r * HH + c0 + 16 * m] =
                    S_h[(r0 + i) * PAD + c0 + 16 * m] + red2(acc[i][m]);
        }
    }

    // x_new = x + x_update / (N-1)
    if (tid < TILE) {
        int r = n0 + tid;
        if (r < NN) {
            const float inv = 1.0f / (float)(NN - 1);
            out[NN * HH + r * 3 + 0] = x[r * 3 + 0] + g_xupd[r * 3 + 0] * inv;
            out[NN * HH + r * 3 + 1] = x[r * 3 + 1] + g_xupd[r * 3 + 1] * inv;
            out[NN * HH + r * 3 + 2] = x[r * 3 + 2] + g_xupd[r * 3 + 2] * inv;
        }
    }
}

// ---------------------------------------------------------------------------

extern "C" void kernel_launch(void* const* d_in, const int* in_sizes, int n_in,
                              void* d_out, int out_size) {
    const float* h   = (const float*)d_in[0];
    const float* x   = (const float*)d_in[1];
    const void*  ei  = d_in[2];
    const float* ew1 = (const float*)d_in[3];
    const float* eb1 = (const float*)d_in[4];
    const float* ew2 = (const float*)d_in[5];
    const float* eb2 = (const float*)d_in[6];
    const float* nw1 = (const float*)d_in[7];
    const float* nb1 = (const float*)d_in[8];
    const float* nw2 = (const float*)d_in[9];
    const float* nb2 = (const float*)d_in[10];
    const float* cw1 = (const float*)d_in[11];
    const float* cb1 = (const float*)d_in[12];
    const float* cw2 = (const float*)d_in[13];
    float* out = (float*)d_out;

    const int smem_edge = (3 * TILE * PAD) * 4 + 8 * HH * 8
                        + (TILE * 5 + TILE * 3) * 4 + 256;
    const int smem_node = (3 * TILE * PAD) * 4 + 8 * HH * 8;

    cudaFuncSetAttribute(edge_kernel, cudaFuncAttributeMaxDynamicSharedMemorySize, smem_edge);
    cudaFuncSetAttribute(node_kernel, cudaFuncAttributeMaxDynamicSharedMemorySize, smem_node);

    const int total = NN * HH + NN * 3;
    zero_kernel<<<(total + 1023) / 1024, 1024>>>(ei);
    edge_kernel<<<EE / TILE, NTHR, smem_edge>>>(h, x, ei, ew1, eb1, ew2, eb2,
                                                cw1, cb1, cw2);
    node_kernel<<<(NN + TILE - 1) / TILE, NTHR, smem_node>>>(h, x, nw1, nb1,
                                                             nw2, nb2, out);
}

// round 5
// speedup vs baseline: 1.3130x; 1.0009x over previous
#include <cuda_runtime.h>

#define NN   20000
#define EE   640000
#define HH   128
#define TILE 64
#define PAD  132
#define NTHR 256

typedef unsigned long long u64;

// Scratch (allocation-free rule: __device__ globals)
__device__ __align__(16) float g_m_i[NN * HH];   // segment-summed m_ij
__device__ __align__(16) float g_xupd[NN * 3];   // segment-summed coord update
__device__ int g_is64;                            // edge_index dtype flag

__device__ __forceinline__ float silu_f(float v) {
    return v * (1.0f / (1.0f + __expf(-v)));
}

// packed fp32x2 FMA: d.lo += a.lo*b.lo ; d.hi += a.hi*b.hi
__device__ __forceinline__ void fma2(u64& d, u64 a, u64 b) {
    asm("fma.rn.f32x2 %0, %1, %2, %0;" : "+l"(d) : "l"(a), "l"(b));
}
__device__ __forceinline__ float red2(u64 v) {
    return __uint_as_float((unsigned)v) + __uint_as_float((unsigned)(v >> 32));
}

// acc[4][8] (f32x2, lo=even-k partial, hi=odd-k partial) +=
//   Sin[64][PAD](cols 0..127) @ W[128][128] (W row-major, k-major, global)
// Weights are staged per 16-k chunk into wbuf2 INTERLEAVED as k-pairs:
//   wbuf2[k2*128 + j] = (W[2k2][j], W[2k2+1][j])
// Thread (r0, c0): rows r0..r0+3, cols c0+16*m (m=0..7).
// Syncs internally; first sync also orders prior smem writes by the block.
__device__ __forceinline__ void gemm2(u64 acc[4][8],
                                      const float* __restrict__ W,
                                      const float* __restrict__ Sin,
                                      float2* __restrict__ wbuf2,
                                      int tid, int r0, int c0)
{
#pragma unroll 1
    for (int k0 = 0; k0 < 128; k0 += 16) {
        __syncthreads();                      // prior wbuf2 readers done
#pragma unroll
        for (int t = 0; t < 4; t++) {
            int idx = tid + t * 256;          // 0..1023 over [8][128]
            int k2 = idx >> 7, j = idx & 127;
            wbuf2[idx] = make_float2(W[(k0 + 2 * k2) * HH + j],
                                     W[(k0 + 2 * k2 + 1) * HH + j]);
        }
        __syncthreads();
#pragma unroll
        for (int k2 = 0; k2 < 8; k2++) {
            u64 bb[8], aa[4];
#pragma unroll
            for (int m = 0; m < 8; m++)
                bb[m] = *(const u64*)&wbuf2[k2 * 128 + c0 + 16 * m];
#pragma unroll
            for (int i = 0; i < 4; i++)
                aa[i] = *(const u64*)&Sin[(r0 + i) * PAD + k0 + 2 * k2];
#pragma unroll
            for (int i = 0; i < 4; i++)
#pragma unroll
                for (int m = 0; m < 8; m++)
                    fma2(acc[i][m], aa[i], bb[m]);
        }
    }
}

// ---------------------------------------------------------------------------
// Kernel 0: zero accumulators + detect edge_index width (int32 vs int64)
// ---------------------------------------------------------------------------
__global__ void zero_kernel(const void* ei) {
    int i = blockIdx.x * blockDim.x + threadIdx.x;
    const int total = NN * HH + NN * 3;
    if (i < total) {
        if (i < NN * HH) g_m_i[i] = 0.0f;
        else             g_xupd[i - NN * HH] = 0.0f;
    }
    if (blockIdx.x == 0 && threadIdx.x == 0) {
        const unsigned* w = (const unsigned*)ei;
        int is64 = 1;
        for (int k = 0; k < 32; k++)
            if (w[2 * k + 1] != 0u) { is64 = 0; break; }
        g_is64 = is64;
    }
}

// ---------------------------------------------------------------------------
// Kernel 1: fused edge pipeline.
// ---------------------------------------------------------------------------
__global__ void __launch_bounds__(NTHR, 2) edge_kernel(
    const float* __restrict__ h, const float* __restrict__ x,
    const void* __restrict__ ei,
    const float* __restrict__ ew1, const float* __restrict__ eb1,
    const float* __restrict__ ew2, const float* __restrict__ eb2,
    const float* __restrict__ cw1, const float* __restrict__ cb1,
    const float* __restrict__ cw2)
{
    extern __shared__ float smem[];
    float*  S_hr  = smem;                     // [64][132]
    float*  S_hc  = S_hr + TILE * PAD;        // [64][132]
    float*  S_act = S_hc + TILE * PAD;        // [64][132]
    float2* wbuf2 = (float2*)(S_act + TILE * PAD);   // [8][128] f32x2
    float*  s_rad = (float*)(wbuf2 + 8 * HH); // [64]
    float*  s_cw  = s_rad + TILE;             // [64]
    float*  s_cd  = s_cw + TILE;              // [64][3]
    int*    s_row = (int*)(s_cd + TILE * 3);  // [64]
    int*    s_col = s_row + TILE;             // [64]

    const int tid = threadIdx.x;
    const int e0  = blockIdx.x * TILE;

    if (tid < TILE) {
        int e = e0 + tid;
        int r, c;
        if (g_is64) {
            const long long* p = (const long long*)ei;
            r = (int)p[e]; c = (int)p[EE + e];
        } else {
            const int* p = (const int*)ei;
            r = p[e]; c = p[EE + e];
        }
        s_row[tid] = r; s_col[tid] = c;
        float dx = x[r * 3 + 0] - x[c * 3 + 0];
        float dy = x[r * 3 + 1] - x[c * 3 + 1];
        float dz = x[r * 3 + 2] - x[c * 3 + 2];
        s_cd[tid * 3 + 0] = dx; s_cd[tid * 3 + 1] = dy; s_cd[tid * 3 + 2] = dz;
        s_rad[tid] = dx * dx + dy * dy + dz * dz;
    }
    __syncthreads();

    // Gather h[row], h[col] tiles (float4)
    const float4* h4 = (const float4*)h;
    for (int i = tid; i < TILE * 32; i += NTHR) {
        int e = i >> 5, q = i & 31;
        *(float4*)&S_hr[e * PAD + q * 4] = h4[s_row[e] * 32 + q];
        *(float4*)&S_hc[e * PAD + q * 4] = h4[s_col[e] * 32 + q];
    }

    const int r0 = (tid >> 4) * 4;   // row group
    const int c0 = tid & 15;         // column base; cols = c0 + 16*m
    u64 acc[4][8];

    // GEMM1 init: eb1 + radial * ew1[256,:]  (both f32x2 halves get half init?
    // No: put full init in lo-half, hi starts at 0, sum at reduction.)
    const float* wlast = ew1 + 256 * HH;
#pragma unroll
    for (int m = 0; m < 8; m++) {
        float b  = eb1[c0 + 16 * m];
        float wl = wlast[c0 + 16 * m];
#pragma unroll
        for (int i = 0; i < 4; i++) {
            float init = b + s_rad[r0 + i] * wl;
            acc[i][m] = (u64)__float_as_uint(init);   // lo=init, hi=0
        }
    }
    gemm2(acc, ew1,            S_hr, wbuf2, tid, r0, c0);   // h[row] part
    gemm2(acc, ew1 + 128 * HH, S_hc, wbuf2, tid, r0, c0);   // h[col] part

    // silu -> S_act
#pragma unroll
    for (int i = 0; i < 4; i++)
#pragma unroll
        for (int m = 0; m < 8; m++)
            S_act[(r0 + i) * PAD + c0 + 16 * m] = silu_f(red2(acc[i][m]));

    // GEMM2
#pragma unroll
    for (int m = 0; m < 8; m++) {
        float b = eb2[c0 + 16 * m];
#pragma unroll
        for (int i = 0; i < 4; i++) acc[i][m] = (u64)__float_as_uint(b);
    }
    gemm2(acc, ew2, S_act, wbuf2, tid, r0, c0);

    // m_ij = silu -> S_hr (gemm2's internal syncs passed all S_hr readers)
#pragma unroll
    for (int i = 0; i < 4; i++)
#pragma unroll
        for (int m = 0; m < 8; m++)
            S_hr[(r0 + i) * PAD + c0 + 16 * m] = silu_f(red2(acc[i][m]));

    // GEMM3 (coord_mlp layer 1)
#pragma unroll
    for (int m = 0; m < 8; m++) {
        float b = cb1[c0 + 16 * m];
#pragma unroll
        for (int i = 0; i < 4; i++) acc[i][m] = (u64)__float_as_uint(b);
    }
    gemm2(acc, cw1, S_hr, wbuf2, tid, r0, c0);

    // coord_weight = silu(t) @ cw2  — in-register, 16-lane shfl reduce
    float cwr[8];
#pragma unroll
    for (int m = 0; m < 8; m++) cwr[m] = cw2[c0 + 16 * m];
#pragma unroll
    for (int i = 0; i < 4; i++) {
        float p = 0.0f;
#pragma unroll
        for (int m = 0; m < 8; m++) p += silu_f(red2(acc[i][m])) * cwr[m];
#pragma unroll
        for (int off = 8; off >= 1; off >>= 1)
            p += __shfl_down_sync(0xffffffffu, p, off);
        if ((tid & 15) == 0) s_cw[r0 + i] = p;
    }
    __syncthreads();

    // Scatter: coordinate update
    if (tid < TILE) {
        int r = s_row[tid];
        float w = s_cw[tid];
        atomicAdd(&g_xupd[r * 3 + 0], s_cd[tid * 3 + 0] * w);
        atomicAdd(&g_xupd[r * 3 + 1], s_cd[tid * 3 + 1] * w);
        atomicAdd(&g_xupd[r * 3 + 2], s_cd[tid * 3 + 2] * w);
    }
    // Scatter: m_i (coalesced 32-wide per edge)
    for (int i = tid; i < TILE * HH; i += NTHR) {
        int e = i >> 7, cc = i & 127;
        atomicAdd(&g_m_i[s_row[e] * HH + cc], S_hr[e * PAD + cc]);
    }
}

// ---------------------------------------------------------------------------
// Kernel 2: node MLP + residual, plus x_new epilogue
// ---------------------------------------------------------------------------
__global__ void __launch_bounds__(NTHR, 2) node_kernel(
    const float* __restrict__ h, const float* __restrict__ x,
    const float* __restrict__ nw1, const float* __restrict__ nb1,
    const float* __restrict__ nw2, const float* __restrict__ nb2,
    float* __restrict__ out)
{
    extern __shared__ float smem[];
    float*  S_h   = smem;
    float*  S_m   = S_h + TILE * PAD;
    float*  S_act = S_m + TILE * PAD;
    float2* wbuf2 = (float2*)(S_act + TILE * PAD);

    const int tid = threadIdx.x;
    const int n0  = blockIdx.x * TILE;

    const float4* h4 = (const float4*)h;
    const float4* m4 = (const float4*)g_m_i;
    for (int i = tid; i < TILE * 32; i += NTHR) {
        int rl = i >> 5, q = i & 31;
        int r = n0 + rl;
        float4 vh = make_float4(0.f, 0.f, 0.f, 0.f);
        float4 vm = vh;
        if (r < NN) { vh = h4[r * 32 + q]; vm = m4[r * 32 + q]; }
        *(float4*)&S_h[rl * PAD + q * 4] = vh;
        *(float4*)&S_m[rl * PAD + q * 4] = vm;
    }

    const int r0 = (tid >> 4) * 4;
    const int c0 = tid & 15;
    u64 acc[4][8];

#pragma unroll
    for (int m = 0; m < 8; m++) {
        float b = nb1[c0 + 16 * m];
#pragma unroll
        for (int i = 0; i < 4; i++) acc[i][m] = (u64)__float_as_uint(b);
    }
    gemm2(acc, nw1,            S_h, wbuf2, tid, r0, c0);
    gemm2(acc, nw1 + 128 * HH, S_m, wbuf2, tid, r0, c0);

#pragma unroll
    for (int i = 0; i < 4; i++)
#pragma unroll
        for (int m = 0; m < 8; m++)
            S_act[(r0 + i) * PAD + c0 + 16 * m] = silu_f(red2(acc[i][m]));

#pragma unroll
    for (int m = 0; m < 8; m++) {
        float b = nb2[c0 + 16 * m];
#pragma unroll
        for (int i = 0; i < 4; i++) acc[i][m] = (u64)__float_as_uint(b);
    }
    gemm2(acc, nw2, S_act, wbuf2, tid, r0, c0);

    // h_new = h + out2
#pragma unroll
    for (int i = 0; i < 4; i++) {
        int r = n0 + r0 + i;
        if (r < NN) {
#pragma unroll
            for (int m = 0; m < 8; m++)
                out[r * HH + c0 + 16 * m] =
                    S_h[(r0 + i) * PAD + c0 + 16 * m] + red2(acc[i][m]);
        }
    }

    // x_new = x + x_update / (N-1)
    if (tid < TILE) {
        int r = n0 + tid;
        if (r < NN) {
            const float inv = 1.0f / (float)(NN - 1);
            out[NN * HH + r * 3 + 0] = x[r * 3 + 0] + g_xupd[r * 3 + 0] * inv;
            out[NN * HH + r * 3 + 1] = x[r * 3 + 1] + g_xupd[r * 3 + 1] * inv;
            out[NN * HH + r * 3 + 2] = x[r * 3 + 2] + g_xupd[r * 3 + 2] * inv;
        }
    }
}

// ---------------------------------------------------------------------------

extern "C" void kernel_launch(void* const* d_in, const int* in_sizes, int n_in,
                              void* d_out, int out_size) {
    const float* h   = (const float*)d_in[0];
    const float* x   = (const float*)d_in[1];
    const void*  ei  = d_in[2];
    const float* ew1 = (const float*)d_in[3];
    const float* eb1 = (const float*)d_in[4];
    const float* ew2 = (const float*)d_in[5];
    const float* eb2 = (const float*)d_in[6];
    const float* nw1 = (const float*)d_in[7];
    const float* nb1 = (const float*)d_in[8];
    const float* nw2 = (const float*)d_in[9];
    const float* nb2 = (const float*)d_in[10];
    const float* cw1 = (const float*)d_in[11];
    const float* cb1 = (const float*)d_in[12];
    const float* cw2 = (const float*)d_in[13];
    float* out = (float*)d_out;

    const int smem_edge = (3 * TILE * PAD) * 4 + 8 * HH * 8
                        + (TILE * 5 + TILE * 3) * 4 + 256;
    const int smem_node = (3 * TILE * PAD) * 4 + 8 * HH * 8;

    cudaFuncSetAttribute(edge_kernel, cudaFuncAttributeMaxDynamicSharedMemorySize, smem_edge);
    cudaFuncSetAttribute(node_kernel, cudaFuncAttributeMaxDynamicSharedMemorySize, smem_node);

    const int total = NN * HH + NN * 3;
    zero_kernel<<<(total + 1023) / 1024, 1024>>>(ei);
    edge_kernel<<<EE / TILE, NTHR, smem_edge>>>(h, x, ei, ew1, eb1, ew2, eb2,
                                                cw1, cb1, cw2);
    node_kernel<<<(NN + TILE - 1) / TILE, NTHR, smem_node>>>(h, x, nw1, nb1,
                                                             nw2, nb2, out);
}

// round 7
// speedup vs baseline: 2.3741x; 1.8082x over previous
#include <cuda_runtime.h>
#include <cuda_bf16.h>

#define NN   20000
#define EE   640000
#define HH   128
#define MT   128            // edges per tile (MMA M)
#define ETHR 512            // edge kernel threads (16 warps)

#define NTILE 64            // node kernel tile
#define NPAD  132
#define NTHR  256

typedef unsigned int u32;
typedef unsigned long long u64;

// Padded bf16 row length for ldmatrix-friendly smem (136*2=272B = 17*16B)
#define KP   136
#define IMG  (128 * KP)            // one [128][136] bf16 image (elements)
#define STAGE_ELEMS (2 * IMG)      // hi+lo image per weight stage

// ---------------- device scratch (allocation-free rule) ----------------
__device__ __align__(16) float g_m_i[NN * HH];
__device__ __align__(16) float g_xupd[NN * 3];
__device__ int g_is64;
// 4 weight stages (W1a, W1b, W2, W3), each [hi [128][136] | lo [128][136]]
__device__ __align__(16) __nv_bfloat16 g_wb[4 * STAGE_ELEMS];

__device__ __forceinline__ float silu_f(float v) {
    return v * (1.0f / (1.0f + __expf(-v)));
}

// ---------------- mma.sync helpers (baseline ISA, sm_80+) ----------------
__device__ __forceinline__ u32 smem_u32(const void* p) {
    u32 a;
    asm("{ .reg .u64 t; cvta.to.shared.u64 t, %1; cvt.u32.u64 %0, t; }"
        : "=r"(a) : "l"(p));
    return a;
}
__device__ __forceinline__ void ldm4(u32* r, u32 addr) {
    asm volatile("ldmatrix.sync.aligned.m8n8.x4.shared.b16 {%0,%1,%2,%3}, [%4];"
                 : "=r"(r[0]), "=r"(r[1]), "=r"(r[2]), "=r"(r[3]) : "r"(addr));
}
__device__ __forceinline__ void mma_bf16(float* c, const u32* a, u32 b0, u32 b1) {
    asm volatile(
        "mma.sync.aligned.m16n8k16.row.col.f32.bf16.bf16.f32 "
        "{%0,%1,%2,%3}, {%4,%5,%6,%7}, {%8,%9}, {%0,%1,%2,%3};"
        : "+f"(c[0]), "+f"(c[1]), "+f"(c[2]), "+f"(c[3])
        : "r"(a[0]), "r"(a[1]), "r"(a[2]), "r"(a[3]), "r"(b0), "r"(b1));
}
__device__ __forceinline__ u32 pack_bf16(float a, float b) {
    __nv_bfloat162 t = __floats2bfloat162_rn(a, b);
    return *(u32*)&t;
}
// split v=a,b into hi/lo bf16 pairs and store to padded images
__device__ __forceinline__ void split_store(char* hiB, char* loB, int m, int n,
                                            float a, float b) {
    __nv_bfloat16 ha = __float2bfloat16(a), hb = __float2bfloat16(b);
    float la = a - __bfloat162float(ha);
    float lb = b - __bfloat162float(hb);
    __nv_bfloat162 hp; hp.x = ha; hp.y = hb;
    u32 off = (u32)(m * KP + n) * 2;
    *(u32*)(hiB + off) = *(u32*)&hp;
    *(u32*)(loB + off) = pack_bf16(la, lb);
}

// ---------------------------------------------------------------------------
// Kernel 0: zero accumulators, detect index width, bake hi/lo weight images
// [n][k] padded to KP (transposed B^T, k contiguous) for ldmatrix.
// ---------------------------------------------------------------------------
__global__ void prep_kernel(const void* ei, const float* ew1,
                            const float* ew2, const float* cw1) {
    int i = blockIdx.x * blockDim.x + threadIdx.x;
    const int total = NN * HH + NN * 3;
    if (i < total) {
        if (i < NN * HH) g_m_i[i] = 0.0f;
        else             g_xupd[i - NN * HH] = 0.0f;
    }
    if (i < 65536) {
        int s = i >> 14, r = i & 16383;
        int k = r >> 7, n = r & 127;
        float v;
        if      (s == 0) v = ew1[k * 128 + n];
        else if (s == 1) v = ew1[(128 + k) * 128 + n];
        else if (s == 2) v = ew2[k * 128 + n];
        else             v = cw1[k * 128 + n];
        __nv_bfloat16 hi = __float2bfloat16(v);
        float lo = v - __bfloat162float(hi);
        __nv_bfloat16* base = g_wb + (size_t)s * STAGE_ELEMS;
        base[n * KP + k]       = hi;
        base[IMG + n * KP + k] = __float2bfloat16(lo);
    }
    if (blockIdx.x == 0 && threadIdx.x == 0) {
        const unsigned* w = (const unsigned*)ei;
        int is64 = 1;
        for (int kk = 0; kk < 32; kk++)
            if (w[2 * kk + 1] != 0u) { is64 = 0; break; }
        g_is64 = is64;
    }
}

// SMEM byte offsets (edge kernel)
#define OFF_AHI 0
#define OFF_ALO (IMG * 2)             // 34816
#define OFF_WHI (2 * IMG * 2)         // 69632
#define OFF_WLO (3 * IMG * 2)         // 104448
#define OFF_MISC (4 * IMG * 2)        // 139264
#define SMEM_EDGE (OFF_MISC + 6656)

// one K=128 GEMM: acc[8][4] += A(hi/lo) @ W(hi/lo)^T, 3-term split
__device__ __forceinline__ void gemm_mma(float acc[8][4],
                                         u32 aHi, u32 aLo, u32 wHi, u32 wLo,
                                         int lane, int wm, int nh)
{
    const int rowA = wm * 16 + (lane & 15);
    const int colA = (lane & 16) ? 8 : 0;
    const u32 aOff = (u32)(rowA * KP + colA) * 2;
    const int rowB = nh * 64 + ((lane & 16) ? 8 : 0) + (lane & 7);
    const int colB = (lane & 8) ? 8 : 0;
    const u32 bOff = (u32)(rowB * KP + colB) * 2;

#pragma unroll
    for (int k0 = 0; k0 < 8; k0++) {
        u32 ah[4], al[4];
        ldm4(ah, aHi + aOff + k0 * 32);
        ldm4(al, aLo + aOff + k0 * 32);
#pragma unroll
        for (int np = 0; np < 4; np++) {
            u32 bh[4], bl[4];
            u32 o = bOff + (u32)np * (16 * KP * 2) + k0 * 32;
            ldm4(bh, wHi + o);
            ldm4(bl, wLo + o);
            mma_bf16(acc[2 * np],     ah, bh[0], bh[1]);
            mma_bf16(acc[2 * np],     ah, bl[0], bl[1]);
            mma_bf16(acc[2 * np],     al, bh[0], bh[1]);
            mma_bf16(acc[2 * np + 1], ah, bh[2], bh[3]);
            mma_bf16(acc[2 * np + 1], ah, bl[2], bl[3]);
            mma_bf16(acc[2 * np + 1], al, bh[2], bh[3]);
        }
    }
}

// ---------------------------------------------------------------------------
// Kernel 1: fused edge pipeline on mma.sync (bf16 hi/lo split, fp32 accum)
// ---------------------------------------------------------------------------
__global__ void __launch_bounds__(ETHR, 1) edge_kernel(
    const float* __restrict__ h, const float* __restrict__ x,
    const void* __restrict__ ei,
    const float* __restrict__ ew1,   // radial-row weights (fp32)
    const float* __restrict__ eb1, const float* __restrict__ eb2,
    const float* __restrict__ cb1, const float* __restrict__ cw2)
{
    extern __shared__ char smem[];
    char*  A_hi = smem + OFF_AHI;
    char*  A_lo = smem + OFF_ALO;
    float* s_eb1 = (float*)(smem + OFF_MISC);
    float* s_eb2 = s_eb1 + 128;
    float* s_cb1 = s_eb2 + 128;
    float* s_wl  = s_cb1 + 128;
    float* s_cw2 = s_wl + 128;
    float* s_rad = s_cw2 + 128;
    float* s_cd  = s_rad + 128;          // [128][3]
    float* s_part = s_cd + 384;          // [128][2]
    int*   s_row = (int*)(s_part + 256);
    int*   s_col = s_row + 128;

    const int tid  = threadIdx.x;
    const int lane = tid & 31;
    const int warp = tid >> 5;
    const int wm   = warp >> 1;          // row group (16 rows)
    const int nh   = warp & 1;           // column half (64 cols)
    const int e0   = blockIdx.x * MT;

    const u32 sb   = smem_u32(smem);
    const u32 aHiA = sb + OFF_AHI, aLoA = sb + OFF_ALO;
    const u32 wHiA = sb + OFF_WHI, wLoA = sb + OFF_WLO;

    // ---- per-tile metadata ----
    if (tid < MT) {
        int e = e0 + tid;
        int r, c;
        if (g_is64) {
            const long long* p = (const long long*)ei;
            r = (int)p[e]; c = (int)p[EE + e];
        } else {
            const int* p = (const int*)ei;
            r = p[e]; c = p[EE + e];
        }
        s_row[tid] = r; s_col[tid] = c;
        float dx = x[r * 3 + 0] - x[c * 3 + 0];
        float dy = x[r * 3 + 1] - x[c * 3 + 1];
        float dz = x[r * 3 + 2] - x[c * 3 + 2];
        s_cd[tid * 3 + 0] = dx; s_cd[tid * 3 + 1] = dy; s_cd[tid * 3 + 2] = dz;
        s_rad[tid] = dx * dx + dy * dy + dz * dz;
        s_eb1[tid] = eb1[tid];
        s_eb2[tid] = eb2[tid];
        s_cb1[tid] = cb1[tid];
        s_wl[tid]  = ew1[256 * 128 + tid];
        s_cw2[tid] = cw2[tid];
    }
    __syncthreads();

    // lane->fragment element mapping
    const int l4 = lane >> 2, l2 = lane & 3;
    const int m0 = wm * 16 + l4, m1 = m0 + 8;

    float acc[8][4];
#pragma unroll
    for (int t = 0; t < 8; t++)
#pragma unroll
        for (int j = 0; j < 4; j++) acc[t][j] = 0.0f;

    // ---- stage W1a + gather h[row] ----
    {
        const float4* ws = (const float4*)g_wb;
        float4* wd = (float4*)(smem + OFF_WHI);
        for (int i = tid; i < 4352; i += ETHR) wd[i] = ws[i];
    }
    {
        int r = tid >> 2, q = (tid & 3) * 32;
        const float4* hb = (const float4*)(h + (size_t)s_row[r] * HH + q);
#pragma unroll
        for (int i = 0; i < 8; i++) {
            float4 f = hb[i];
            int c = q + i * 4;
            split_store(A_hi, A_lo, r, c,     f.x, f.y);
            split_store(A_hi, A_lo, r, c + 2, f.z, f.w);
        }
    }
    __syncthreads();
    gemm_mma(acc, aHiA, aLoA, wHiA, wLoA, lane, wm, nh);
    __syncthreads();

    // ---- stage W1b + gather h[col] ----
    {
        const float4* ws = (const float4*)(g_wb + STAGE_ELEMS);
        float4* wd = (float4*)(smem + OFF_WHI);
        for (int i = tid; i < 4352; i += ETHR) wd[i] = ws[i];
    }
    {
        int r = tid >> 2, q = (tid & 3) * 32;
        const float4* hb = (const float4*)(h + (size_t)s_col[r] * HH + q);
#pragma unroll
        for (int i = 0; i < 8; i++) {
            float4 f = hb[i];
            int c = q + i * 4;
            split_store(A_hi, A_lo, r, c,     f.x, f.y);
            split_store(A_hi, A_lo, r, c + 2, f.z, f.w);
        }
    }
    __syncthreads();
    gemm_mma(acc, aHiA, aLoA, wHiA, wLoA, lane, wm, nh);
    __syncthreads();

    // ---- epilogue1: t1 = silu(acc + eb1 + rad*wl) -> A ; stage W2 ----
    {
        float r0 = s_rad[m0], r1 = s_rad[m1];
#pragma unroll
        for (int nt = 0; nt < 8; nt++) {
            int n = nh * 64 + nt * 8 + 2 * l2;
            float b0 = s_eb1[n], b1 = s_eb1[n + 1];
            float w0 = s_wl[n],  w1 = s_wl[n + 1];
            float v00 = silu_f(acc[nt][0] + b0 + r0 * w0);
            float v01 = silu_f(acc[nt][1] + b1 + r0 * w1);
            float v10 = silu_f(acc[nt][2] + b0 + r1 * w0);
            float v11 = silu_f(acc[nt][3] + b1 + r1 * w1);
            split_store(A_hi, A_lo, m0, n, v00, v01);
            split_store(A_hi, A_lo, m1, n, v10, v11);
            acc[nt][0] = acc[nt][1] = acc[nt][2] = acc[nt][3] = 0.0f;
        }
    }
    {
        const float4* ws = (const float4*)(g_wb + 2 * STAGE_ELEMS);
        float4* wd = (float4*)(smem + OFF_WHI);
        for (int i = tid; i < 4352; i += ETHR) wd[i] = ws[i];
    }
    __syncthreads();
    gemm_mma(acc, aHiA, aLoA, wHiA, wLoA, lane, wm, nh);
    __syncthreads();

    // ---- epilogue2: m_ij = silu(acc + eb2); atomics m_i; -> A ; stage W3 ----
    {
        int rA = s_row[m0], rB = s_row[m1];
        float* gA = g_m_i + (size_t)rA * HH;
        float* gB = g_m_i + (size_t)rB * HH;
#pragma unroll
        for (int nt = 0; nt < 8; nt++) {
            int n = nh * 64 + nt * 8 + 2 * l2;
            float b0 = s_eb2[n], b1 = s_eb2[n + 1];
            float v00 = silu_f(acc[nt][0] + b0);
            float v01 = silu_f(acc[nt][1] + b1);
            float v10 = silu_f(acc[nt][2] + b0);
            float v11 = silu_f(acc[nt][3] + b1);
            atomicAdd(gA + n,     v00);
            atomicAdd(gA + n + 1, v01);
            atomicAdd(gB + n,     v10);
            atomicAdd(gB + n + 1, v11);
            split_store(A_hi, A_lo, m0, n, v00, v01);
            split_store(A_hi, A_lo, m1, n, v10, v11);
            acc[nt][0] = acc[nt][1] = acc[nt][2] = acc[nt][3] = 0.0f;
        }
    }
    {
        const float4* ws = (const float4*)(g_wb + 3 * STAGE_ELEMS);
        float4* wd = (float4*)(smem + OFF_WHI);
        for (int i = tid; i < 4352; i += ETHR) wd[i] = ws[i];
    }
    __syncthreads();
    gemm_mma(acc, aHiA, aLoA, wHiA, wLoA, lane, wm, nh);

    // ---- epilogue3: coord_weight = silu(acc + cb1) . cw2 ----
    {
        float p0 = 0.0f, p1 = 0.0f;
#pragma unroll
        for (int nt = 0; nt < 8; nt++) {
            int n = nh * 64 + nt * 8 + 2 * l2;
            float b0 = s_cb1[n], b1 = s_cb1[n + 1];
            float c0 = s_cw2[n], c1 = s_cw2[n + 1];
            p0 += silu_f(acc[nt][0] + b0) * c0 + silu_f(acc[nt][1] + b1) * c1;
            p1 += silu_f(acc[nt][2] + b0) * c0 + silu_f(acc[nt][3] + b1) * c1;
        }
        p0 += __shfl_xor_sync(0xffffffffu, p0, 1);
        p0 += __shfl_xor_sync(0xffffffffu, p0, 2);
        p1 += __shfl_xor_sync(0xffffffffu, p1, 1);
        p1 += __shfl_xor_sync(0xffffffffu, p1, 2);
        if (l2 == 0) {
            s_part[m0 * 2 + nh] = p0;
            s_part[m1 * 2 + nh] = p1;
        }
    }
    __syncthreads();

    if (tid < MT) {
        float w = s_part[tid * 2] + s_part[tid * 2 + 1];
        int r = s_row[tid];
        atomicAdd(&g_xupd[r * 3 + 0], s_cd[tid * 3 + 0] * w);
        atomicAdd(&g_xupd[r * 3 + 1], s_cd[tid * 3 + 1] * w);
        atomicAdd(&g_xupd[r * 3 + 2], s_cd[tid * 3 + 2] * w);
    }
}

// ---------------------------------------------------------------------------
// Kernel 2: node MLP + residual + x epilogue (SIMT f32x2 — small workload)
// ---------------------------------------------------------------------------
__device__ __forceinline__ void fma2(u64& d, u64 a, u64 b) {
    asm("fma.rn.f32x2 %0, %1, %2, %0;" : "+l"(d) : "l"(a), "l"(b));
}
__device__ __forceinline__ float red2(u64 v) {
    return __uint_as_float((unsigned)v) + __uint_as_float((unsigned)(v >> 32));
}

__device__ __forceinline__ void gemm2(u64 acc[4][8],
                                      const float* __restrict__ W,
                                      const float* __restrict__ Sin,
                                      float2* __restrict__ wbuf2,
                                      int tid, int r0, int c0)
{
#pragma unroll 1
    for (int k0 = 0; k0 < 128; k0 += 16) {
        __syncthreads();
#pragma unroll
        for (int t = 0; t < 4; t++) {
            int idx = tid + t * 256;
            int k2 = idx >> 7, j = idx & 127;
            wbuf2[idx] = make_float2(W[(k0 + 2 * k2) * HH + j],
                                     W[(k0 + 2 * k2 + 1) * HH + j]);
        }
        __syncthreads();
#pragma unroll
        for (int k2 = 0; k2 < 8; k2++) {
            u64 bb[8], aa[4];
#pragma unroll
            for (int m = 0; m < 8; m++)
                bb[m] = *(const u64*)&wbuf2[k2 * 128 + c0 + 16 * m];
#pragma unroll
            for (int i = 0; i < 4; i++)
                aa[i] = *(const u64*)&Sin[(r0 + i) * NPAD + k0 + 2 * k2];
#pragma unroll
            for (int i = 0; i < 4; i++)
#pragma unroll
                for (int m = 0; m < 8; m++)
                    fma2(acc[i][m], aa[i], bb[m]);
        }
    }
}

__global__ void __launch_bounds__(NTHR, 2) node_kernel(
    const float* __restrict__ h, const float* __restrict__ x,
    const float* __restrict__ nw1, const float* __restrict__ nb1,
    const float* __restrict__ nw2, const float* __restrict__ nb2,
    float* __restrict__ out)
{
    extern __shared__ float smemf[];
    float*  S_h   = smemf;
    float*  S_m   = S_h + NTILE * NPAD;
    float*  S_act = S_m + NTILE * NPAD;
    float2* wbuf2 = (float2*)(S_act + NTILE * NPAD);

    const int tid = threadIdx.x;
    const int n0  = blockIdx.x * NTILE;

    const float4* h4 = (const float4*)h;
    const float4* m4 = (const float4*)g_m_i;
    for (int i = tid; i < NTILE * 32; i += NTHR) {
        int rl = i >> 5, q = i & 31;
        int r = n0 + rl;
        float4 vh = make_float4(0.f, 0.f, 0.f, 0.f);
        float4 vm = vh;
        if (r < NN) { vh = h4[r * 32 + q]; vm = m4[r * 32 + q]; }
        *(float4*)&S_h[rl * NPAD + q * 4] = vh;
        *(float4*)&S_m[rl * NPAD + q * 4] = vm;
    }

    const int r0 = (tid >> 4) * 4;
    const int c0 = tid & 15;
    u64 acc[4][8];

#pragma unroll
    for (int m = 0; m < 8; m++) {
        float b = nb1[c0 + 16 * m];
#pragma unroll
        for (int i = 0; i < 4; i++) acc[i][m] = (u64)__float_as_uint(b);
    }
    gemm2(acc, nw1,            S_h, wbuf2, tid, r0, c0);
    gemm2(acc, nw1 + 128 * HH, S_m, wbuf2, tid, r0, c0);

#pragma unroll
    for (int i = 0; i < 4; i++)
#pragma unroll
        for (int m = 0; m < 8; m++)
            S_act[(r0 + i) * NPAD + c0 + 16 * m] = silu_f(red2(acc[i][m]));

#pragma unroll
    for (int m = 0; m < 8; m++) {
        float b = nb2[c0 + 16 * m];
#pragma unroll
        for (int i = 0; i < 4; i++) acc[i][m] = (u64)__float_as_uint(b);
    }
    gemm2(acc, nw2, S_act, wbuf2, tid, r0, c0);

#pragma unroll
    for (int i = 0; i < 4; i++) {
        int r = n0 + r0 + i;
        if (r < NN) {
#pragma unroll
            for (int m = 0; m < 8; m++)
                out[r * HH + c0 + 16 * m] =
                    S_h[(r0 + i) * NPAD + c0 + 16 * m] + red2(acc[i][m]);
        }
    }

    if (tid < NTILE) {
        int r = n0 + tid;
        if (r < NN) {
            const float inv = 1.0f / (float)(NN - 1);
            out[NN * HH + r * 3 + 0] = x[r * 3 + 0] + g_xupd[r * 3 + 0] * inv;
            out[NN * HH + r * 3 + 1] = x[r * 3 + 1] + g_xupd[r * 3 + 1] * inv;
            out[NN * HH + r * 3 + 2] = x[r * 3 + 2] + g_xupd[r * 3 + 2] * inv;
        }
    }
}

// ---------------------------------------------------------------------------

extern "C" void kernel_launch(void* const* d_in, const int* in_sizes, int n_in,
                              void* d_out, int out_size) {
    const float* h   = (const float*)d_in[0];
    const float* x   = (const float*)d_in[1];
    const void*  ei  = d_in[2];
    const float* ew1 = (const float*)d_in[3];
    const float* eb1 = (const float*)d_in[4];
    const float* ew2 = (const float*)d_in[5];
    const float* eb2 = (const float*)d_in[6];
    const float* nw1 = (const float*)d_in[7];
    const float* nb1 = (const float*)d_in[8];
    const float* nw2 = (const float*)d_in[9];
    const float* nb2 = (const float*)d_in[10];
    const float* cw1 = (const float*)d_in[11];
    const float* cb1 = (const float*)d_in[12];
    const float* cw2 = (const float*)d_in[13];
    float* out = (float*)d_out;

    const int smem_node = (3 * NTILE * NPAD) * 4 + 8 * HH * 8;

    cudaFuncSetAttribute(edge_kernel, cudaFuncAttributeMaxDynamicSharedMemorySize, SMEM_EDGE);
    cudaFuncSetAttribute(node_kernel, cudaFuncAttributeMaxDynamicSharedMemorySize, smem_node);

    const int total = NN * HH + NN * 3;
    prep_kernel<<<(total + 255) / 256, 256>>>(ei, ew1, ew2, cw1);
    edge_kernel<<<EE / MT, ETHR, SMEM_EDGE>>>(h, x, ei, ew1, eb1, eb2, cb1, cw2);
    node_kernel<<<(NN + NTILE - 1) / NTILE, NTHR, smem_node>>>(h, x, nw1, nb1,
                                                               nw2, nb2, out);
}